// round 13
// baseline (speedup 1.0000x reference)
#include <cuda_runtime.h>
#include <cuda_bf16.h>
#include <math.h>
#include <stdint.h>

#define kNA 8192
#define kNT 8192
#define kD  256
#define kH  128
#define kSeg 32
#define kSegRows 256
#define INV_EPS 10.0f
#define NEGINF -3.402823466e38f

__device__ float g_q[kNA * kD];
__device__ float g_k[kNT * kD];
__device__ float g_h[kNA * kH];
__device__ float g_logits[kNA];
__device__ float g_logb[kNA];
__device__ float g_f[kNA];
__device__ float g_g[kNT];
__device__ float g_M[67108864];
__device__ float g_pm[kSeg * kNT];
__device__ float g_ps[kSeg * kNT];
__device__ __nv_bfloat16 g_qs[2][kNA * kD];
__device__ __nv_bfloat16 g_ks[2][kNT * kD];
__device__ unsigned int g_bar_cnt = 0;
__device__ unsigned int g_bar_gen = 0;

// ---------------- helpers ----------------
__device__ __forceinline__ uint32_t smem_u32(const void* p) {
    uint32_t a;
    asm("{ .reg .u64 t; cvta.to.shared.u64 t, %1; cvt.u32.u64 %0, t; }" : "=r"(a) : "l"(p));
    return a;
}
__device__ __forceinline__ void cp16(uint32_t s, const void* g) {
    asm volatile("cp.async.cg.shared.global [%0], [%1], 16;" :: "r"(s), "l"(g));
}
__device__ __forceinline__ void ldm4(uint32_t& r0, uint32_t& r1, uint32_t& r2,
                                     uint32_t& r3, uint32_t a) {
    asm volatile("ldmatrix.sync.aligned.m8n8.x4.shared.b16 {%0,%1,%2,%3}, [%4];"
                 : "=r"(r0), "=r"(r1), "=r"(r2), "=r"(r3) : "r"(a));
}
__device__ __forceinline__ void mma16816(float* c, const uint32_t* a, const uint32_t* b) {
    asm volatile("mma.sync.aligned.m16n8k16.row.col.f32.bf16.bf16.f32 "
                 "{%0,%1,%2,%3}, {%4,%5,%6,%7}, {%8,%9}, {%0,%1,%2,%3};"
                 : "+f"(c[0]), "+f"(c[1]), "+f"(c[2]), "+f"(c[3])
                 : "r"(a[0]), "r"(a[1]), "r"(a[2]), "r"(a[3]), "r"(b[0]), "r"(b[1]));
}

// grid-wide spin barrier (all blocks guaranteed resident via launch_bounds)
__device__ __forceinline__ void grid_barrier(int nb) {
    __syncthreads();
    if (threadIdx.x == 0) {
        unsigned int gen = atomicAdd(&g_bar_gen, 0u);
        __threadfence();
        unsigned int t = atomicAdd(&g_bar_cnt, 1u);
        if (t == (unsigned)nb - 1u) {
            atomicExch(&g_bar_cnt, 0u);
            __threadfence();
            atomicAdd(&g_bar_gen, 1u);
        } else {
            while (atomicAdd(&g_bar_gen, 0u) == gen) { __nanosleep(64); }
        }
        __threadfence();
    }
    __syncthreads();
}

// ---------------- small SIMT GEMM (q,k,h) ----------------
template<bool RELU>
__global__ void __launch_bounds__(256, 2) gemm128_kernel(
    const float* __restrict__ A, const float* __restrict__ B,
    const float* __restrict__ bias, float* __restrict__ C, int N, int K)
{
    __shared__ float As[16][130];
    __shared__ float Bs[16][130];
    const int tid = threadIdx.x, tx = tid & 15, ty = tid >> 4;
    const int m0 = blockIdx.y * 128, n0 = blockIdx.x * 128;
    const int lr = tid >> 2, lk = (tid & 3) << 2;
    float acc[8][8];
#pragma unroll
    for (int i = 0; i < 8; i++)
#pragma unroll
        for (int j = 0; j < 8; j++) acc[i][j] = 0.f;
    for (int k0 = 0; k0 < K; k0 += 16) {
#pragma unroll
        for (int h = 0; h < 2; h++) {
            int row = lr + h * 64;
            float4 v = *reinterpret_cast<const float4*>(A + (size_t)(m0 + row) * K + k0 + lk);
            As[lk + 0][row] = v.x; As[lk + 1][row] = v.y;
            As[lk + 2][row] = v.z; As[lk + 3][row] = v.w;
        }
        {
            int kk = tid >> 4, nx = (tid & 15) << 2;
#pragma unroll
            for (int h = 0; h < 2; h++) {
                int n = nx + h * 64;
                float4 v = *reinterpret_cast<const float4*>(B + (size_t)(k0 + kk) * N + n0 + n);
                Bs[kk][n + 0] = v.x; Bs[kk][n + 1] = v.y;
                Bs[kk][n + 2] = v.z; Bs[kk][n + 3] = v.w;
            }
        }
        __syncthreads();
#pragma unroll
        for (int kk = 0; kk < 16; kk++) {
            float a[8], b[8];
#pragma unroll
            for (int e = 0; e < 4; e++) {
                a[e] = As[kk][ty * 4 + e];     a[e + 4] = As[kk][ty * 4 + 64 + e];
                b[e] = Bs[kk][tx * 4 + e];     b[e + 4] = Bs[kk][tx * 4 + 64 + e];
            }
#pragma unroll
            for (int i = 0; i < 8; i++)
#pragma unroll
                for (int j = 0; j < 8; j++) acc[i][j] += a[i] * b[j];
        }
        __syncthreads();
    }
#pragma unroll
    for (int i = 0; i < 8; i++) {
        int row = m0 + ty * 4 + (i < 4 ? i : i - 4 + 64);
#pragma unroll
        for (int jh = 0; jh < 2; jh++) {
            int col = n0 + tx * 4 + jh * 64;
            float4 v;
            v.x = acc[i][jh * 4 + 0] + bias[col + 0];
            v.y = acc[i][jh * 4 + 1] + bias[col + 1];
            v.z = acc[i][jh * 4 + 2] + bias[col + 2];
            v.w = acc[i][jh * 4 + 3] + bias[col + 3];
            if (RELU) {
                v.x = fmaxf(v.x, 0.f); v.y = fmaxf(v.y, 0.f);
                v.z = fmaxf(v.z, 0.f); v.w = fmaxf(v.w, 0.f);
            }
            *reinterpret_cast<float4*>(C + (size_t)row * N + col) = v;
        }
    }
}

// ---------------- bf16x2 split ----------------
__global__ void __launch_bounds__(256) split2_kernel(
    const float* __restrict__ x, __nv_bfloat16* __restrict__ h0,
    __nv_bfloat16* __restrict__ l0)
{
    int i = (blockIdx.x * 256 + threadIdx.x) * 4;
    float4 v = *reinterpret_cast<const float4*>(x + i);
    float vs[4] = {v.x, v.y, v.z, v.w};
    __nv_bfloat16 hh[4], ll[4];
#pragma unroll
    for (int c = 0; c < 4; c++) {
        __nv_bfloat16 h = __float2bfloat16(vs[c]);
        float r = vs[c] - __bfloat162float(h);
        hh[c] = h; ll[c] = __float2bfloat16(r);
    }
    *reinterpret_cast<__nv_bfloat162*>(h0 + i)     = __nv_bfloat162{hh[0], hh[1]};
    *reinterpret_cast<__nv_bfloat162*>(h0 + i + 2) = __nv_bfloat162{hh[2], hh[3]};
    *reinterpret_cast<__nv_bfloat162*>(l0 + i)     = __nv_bfloat162{ll[0], ll[1]};
    *reinterpret_cast<__nv_bfloat162*>(l0 + i + 2) = __nv_bfloat162{ll[2], ll[3]};
}

// ---------------- mma.sync GEMM: M = -20 q k^T (bf16x2, 4 terms) -----------
#define CH_BYTES 20480
#define MG_SMEM  40960

__device__ __forceinline__ void ld_chunk(int c, int m0, int n0, uint32_t sb, int tid)
{
    int term = c >> 3, kc = (c & 7) * 32;
    int at = term >> 1;          // {0,0,1,1}
    int bt = term & 1;           // {0,1,0,1}
    const __nv_bfloat16* A = &g_qs[at][0] + (size_t)m0 * kD + kc;
    const __nv_bfloat16* B = &g_ks[bt][0] + (size_t)n0 * kD + kc;
    uint32_t base = sb + (c & 1) * CH_BYTES;
#pragma unroll
    for (int i = 0; i < 4; i++) {
        int idx = i * 256 + tid;
        int mat = idx >> 9, j = idx & 511;
        int row = j >> 2, seg = j & 3;
        const __nv_bfloat16* src = (mat ? B : A) + (size_t)row * kD + seg * 8;
        cp16(base + mat * 10240 + row * 80 + seg * 16, src);
    }
    asm volatile("cp.async.commit_group;" ::: "memory");
}

__global__ void __launch_bounds__(256) mgemm_kernel()
{
    extern __shared__ char smem[];
    uint32_t sb = smem_u32(smem);
    const int tid = threadIdx.x, wid = tid >> 5, lane = tid & 31;
    const int wm = wid & 1, wn = wid >> 1;
    const int m0 = blockIdx.y * 128, n0 = blockIdx.x * 128;

    float acc[4][4][4];
#pragma unroll
    for (int i = 0; i < 4; i++)
#pragma unroll
        for (int j = 0; j < 4; j++)
#pragma unroll
            for (int e = 0; e < 4; e++) acc[i][j][e] = 0.f;

    const int a_row = lane & 15;
    const int a_kb  = (lane >> 4) * 16;
    const int b_row = (lane & 7) + ((lane >> 4) << 3);
    const int b_kb  = ((lane >> 3) & 1) * 16;

    ld_chunk(0, m0, n0, sb, tid);
#pragma unroll 1
    for (int c = 0; c < 32; c++) {
        if (c + 1 < 32) {
            ld_chunk(c + 1, m0, n0, sb, tid);
            asm volatile("cp.async.wait_group 1;" ::: "memory");
        } else {
            asm volatile("cp.async.wait_group 0;" ::: "memory");
        }
        __syncthreads();
        uint32_t bufA = sb + (c & 1) * CH_BYTES;
        uint32_t bufB = bufA + 10240;
#pragma unroll
        for (int ks = 0; ks < 2; ks++) {
            uint32_t afr[4][4], bfr[2][4];
#pragma unroll
            for (int mt = 0; mt < 4; mt++)
                ldm4(afr[mt][0], afr[mt][1], afr[mt][2], afr[mt][3],
                     bufA + (wm * 64 + mt * 16 + a_row) * 80 + ks * 32 + a_kb);
#pragma unroll
            for (int p = 0; p < 2; p++)
                ldm4(bfr[p][0], bfr[p][1], bfr[p][2], bfr[p][3],
                     bufB + (wn * 32 + p * 16 + b_row) * 80 + ks * 32 + b_kb);
#pragma unroll
            for (int mt = 0; mt < 4; mt++)
#pragma unroll
                for (int nt = 0; nt < 4; nt++)
                    mma16816(acc[mt][nt], afr[mt], &bfr[nt >> 1][(nt & 1) * 2]);
        }
        __syncthreads();
    }

    float* stg = reinterpret_cast<float*>(smem);
#pragma unroll 1
    for (int h = 0; h < 2; h++) {
        if (wm == h) {
#pragma unroll
            for (int mt = 0; mt < 4; mt++)
#pragma unroll
                for (int nt = 0; nt < 4; nt++) {
                    int r0 = mt * 16 + (lane >> 2);
                    int cc = wn * 32 + nt * 8 + (lane & 3) * 2;
                    stg[r0 * 132 + cc]           = acc[mt][nt][0];
                    stg[r0 * 132 + cc + 1]       = acc[mt][nt][1];
                    stg[(r0 + 8) * 132 + cc]     = acc[mt][nt][2];
                    stg[(r0 + 8) * 132 + cc + 1] = acc[mt][nt][3];
                }
        }
        __syncthreads();
#pragma unroll
        for (int it = 0; it < 8; it++) {
            int idx = it * 256 + tid;
            int r = idx >> 5, c4 = idx & 31;
            float4 v = *reinterpret_cast<const float4*>(stg + r * 132 + c4 * 4);
            v.x *= -20.f; v.y *= -20.f; v.z *= -20.f; v.w *= -20.f;
            *reinterpret_cast<float4*>(
                g_M + (size_t)(m0 + h * 64 + r) * kNT + n0 + c4 * 4) = v;
        }
        __syncthreads();
    }
}

// ---------------- logits / softmax / g init ----------------
__global__ void logits_kernel(const float* __restrict__ W2, const float* __restrict__ b2)
{
    int warp = threadIdx.x >> 5, lane = threadIdx.x & 31;
    int i = blockIdx.x * 8 + warp;
    const float* hr = g_h + (size_t)i * kH;
    float acc = 0.f;
#pragma unroll
    for (int d = lane; d < kH; d += 32) acc += hr[d] * W2[d];
#pragma unroll
    for (int off = 16; off; off >>= 1) acc += __shfl_down_sync(0xffffffffu, acc, off);
    if (lane == 0) g_logits[i] = acc + b2[0];
}

__global__ void softmax_log_kernel()
{
    __shared__ float red[1024];
    int t = threadIdx.x;
    float m = NEGINF;
    for (int i = t; i < kNA; i += 1024) m = fmaxf(m, g_logits[i]);
    red[t] = m; __syncthreads();
    for (int off = 512; off; off >>= 1) {
        if (t < off) red[t] = fmaxf(red[t], red[t + off]);
        __syncthreads();
    }
    float gm = red[0]; __syncthreads();
    float sum = 0.f;
    for (int i = t; i < kNA; i += 1024) sum += __expf(g_logits[i] - gm);
    red[t] = sum; __syncthreads();
    for (int off = 512; off; off >>= 1) {
        if (t < off) red[t] += red[t + off];
        __syncthreads();
    }
    float lse = gm + logf(red[0]);
    for (int i = t; i < kNA; i += 1024) g_logb[i] = g_logits[i] - lse;
}

__global__ void ginit_kernel()
{
    int warp = threadIdx.x >> 5, lane = threadIdx.x & 31;
    int j = blockIdx.x * 8 + warp;
    const float* kr = g_k + (size_t)j * kD;
    float acc = 0.f;
#pragma unroll
    for (int d = lane; d < kD; d += 32) { float v = kr[d]; acc += v * v; }
#pragma unroll
    for (int off = 16; off; off >>= 1) acc += __shfl_down_sync(0xffffffffu, acc, off);
    if (lane == 0) g_g[j] = INV_EPS * acc;
}

// ---------------- persistent Sinkhorn: 50 iterations, one launch ------------
__global__ void __launch_bounds__(256, 4) sinkhorn_kernel(int nb, float log_a)
{
    const int t = threadIdx.x;
    const int bid = blockIdx.x;
    __shared__ float sm[256], ss[256];

#pragma unroll 1
    for (int it = 0; it < 50; it++) {
        // ---- ROW phase: f_i = logb_i - lse_j(M_ij + g_j), 4 rows per item ----
#pragma unroll 1
        for (int item = bid; item < 2048; item += nb) {
            const int i0 = item * 4;
            const float4* g4 = reinterpret_cast<const float4*>(g_g);
            float m[4], s[4];
#pragma unroll
            for (int r = 0; r < 4; r++) { m[r] = NEGINF; s[r] = 0.f; }
#pragma unroll
            for (int c = 0; c < 8; c++) {
                const int p = c * 256 + t;
                float4 gv = g4[p];
#pragma unroll
                for (int r = 0; r < 4; r++) {
                    float4 mv = reinterpret_cast<const float4*>(
                        g_M + (size_t)(i0 + r) * kNT)[p];
                    float x0 = mv.x + gv.x, x1 = mv.y + gv.y;
                    float x2 = mv.z + gv.z, x3 = mv.w + gv.w;
                    float lm = fmaxf(fmaxf(x0, x1), fmaxf(x2, x3));
                    float mn = fmaxf(m[r], lm);
                    float acc = __expf(x0 - mn) + __expf(x1 - mn)
                              + __expf(x2 - mn) + __expf(x3 - mn);
                    s[r] = s[r] * __expf(m[r] - mn) + acc;
                    m[r] = mn;
                }
            }
#pragma unroll 1
            for (int r = 0; r < 4; r++) {
                sm[t] = m[r]; ss[t] = s[r];
                __syncthreads();
                for (int off = 128; off; off >>= 1) {
                    if (t < off) {
                        float m2 = sm[t + off];
                        float mn = fmaxf(sm[t], m2);
                        ss[t] = ss[t] * __expf(sm[t] - mn) + ss[t + off] * __expf(m2 - mn);
                        sm[t] = mn;
                    }
                    __syncthreads();
                }
                if (t == 0) g_f[i0 + r] = g_logb[i0 + r] - (sm[0] + logf(ss[0]));
                __syncthreads();
            }
        }
        grid_barrier(nb);

        // ---- COL phase: per (jtile, seg) partial LSE over 256 rows ----
#pragma unroll 1
        for (int item = bid; item < 1024; item += nb) {
            const int jt = item & 31, seg = item >> 5;
            const int j = jt * 256 + t;
            const int r0 = seg * kSegRows;
            sm[t] = g_f[r0 + t];            // reuse sm as f-stage
            __syncthreads();
            const float* p = g_M + (size_t)r0 * kNT + j;
            float m = NEGINF, s = 0.f;
            for (int rb = 0; rb < kSegRows; rb += 8) {
                float x[8];
#pragma unroll
                for (int r = 0; r < 8; r++)
                    x[r] = p[(size_t)(rb + r) * kNT] + sm[rb + r];
                float lm = x[0];
#pragma unroll
                for (int r = 1; r < 8; r++) lm = fmaxf(lm, x[r]);
                float mn = fmaxf(m, lm);
                float acc = 0.f;
#pragma unroll
                for (int r = 0; r < 8; r++) acc += __expf(x[r] - mn);
                s = s * __expf(m - mn) + acc;
                m = mn;
            }
            g_pm[seg * kNT + j] = m;
            g_ps[seg * kNT + j] = s;
            __syncthreads();
        }
        grid_barrier(nb);

        // ---- COMBINE phase: g_j = log_a - lse over 32 segments ----
#pragma unroll 1
        for (int item = bid; item < 32; item += nb) {
            int j = item * 256 + t;
            float m = NEGINF;
#pragma unroll
            for (int sg = 0; sg < kSeg; sg++) m = fmaxf(m, g_pm[sg * kNT + j]);
            float acc = 0.f;
#pragma unroll
            for (int sg = 0; sg < kSeg; sg++)
                acc += g_ps[sg * kNT + j] * __expf(g_pm[sg * kNT + j] - m);
            g_g[j] = log_a - (m + logf(acc));
        }
        grid_barrier(nb);
    }
}

// ---------------- final T ----------------
__global__ void __launch_bounds__(256) final_T_kernel(float* __restrict__ out,
                                                      float inv_total)
{
    int i = blockIdx.y;
    int p = blockIdx.x * 256 + threadIdx.x;
    float fi = g_f[i];
    float4 mv = reinterpret_cast<const float4*>(g_M + (size_t)i * kNT)[p];
    float4 gv = reinterpret_cast<const float4*>(g_g)[p];
    float4 o;
    o.x = __expf((fi + gv.x) + mv.x) * inv_total;
    o.y = __expf((fi + gv.y) + mv.y) * inv_total;
    o.z = __expf((fi + gv.z) + mv.z) * inv_total;
    o.w = __expf((fi + gv.w) + mv.w) * inv_total;
    reinterpret_cast<float4*>(out + (size_t)i * kNT)[p] = o;
}

// ---------------- host ----------------
extern "C" void kernel_launch(void* const* d_in, const int* in_sizes, int n_in,
                              void* d_out, int out_size)
{
    const float* Aemb = (const float*)d_in[0];
    const float* Temb = (const float*)d_in[1];
    const float* Wq   = (const float*)d_in[2];
    const float* bq   = (const float*)d_in[3];
    const float* Wk   = (const float*)d_in[4];
    const float* bk   = (const float*)d_in[5];
    const float* W1   = (const float*)d_in[6];
    const float* b1   = (const float*)d_in[7];
    const float* W2   = (const float*)d_in[8];
    const float* b2   = (const float*)d_in[9];
    float* out = (float*)d_out;

    float *pq, *pk, *ph;
    __nv_bfloat16 *pqs, *pks;
    cudaGetSymbolAddress((void**)&pq, g_q);
    cudaGetSymbolAddress((void**)&pk, g_k);
    cudaGetSymbolAddress((void**)&ph, g_h);
    cudaGetSymbolAddress((void**)&pqs, g_qs);
    cudaGetSymbolAddress((void**)&pks, g_ks);

    int sms = 148;
    cudaDeviceGetAttribute(&sms, cudaDevAttrMultiProcessorCount, 0);
    int nb = sms * 4;

    gemm128_kernel<false><<<dim3(2, 64), 256>>>(Aemb, Wq, bq, pq, 256, 256);
    gemm128_kernel<false><<<dim3(2, 64), 256>>>(Temb, Wk, bk, pk, 256, 256);
    gemm128_kernel<true ><<<dim3(1, 64), 256>>>(Aemb, W1, b1, ph, 128, 256);
    logits_kernel<<<1024, 256>>>(W2, b2);
    softmax_log_kernel<<<1, 1024>>>();
    ginit_kernel<<<1024, 256>>>();

    split2_kernel<<<2048, 256>>>(pq, pqs, pqs + kNA * kD);
    split2_kernel<<<2048, 256>>>(pk, pks, pks + kNT * kD);

    mgemm_kernel<<<dim3(64, 64), 256, MG_SMEM>>>();

    const float log_a = logf(1.0f / 8192.0f + 1e-20f);
    sinkhorn_kernel<<<nb, 256>>>(nb, log_a);

    final_T_kernel<<<dim3(8, 8192), 256>>>(out, 1.0f / (1.0f + 1e-8f));
}

// round 14
// speedup vs baseline: 1.3270x; 1.3270x over previous
#include <cuda_runtime.h>
#include <cuda_bf16.h>
#include <math.h>
#include <stdint.h>

#define kNA 8192
#define kNT 8192
#define kD  256
#define kH  128
#define kSeg 32
#define kSegRows 256
#define INV_EPS 10.0f
#define NEGINF -3.402823466e38f

__device__ float g_q[kNA * kD];
__device__ float g_k[kNT * kD];
__device__ float g_h[kNA * kH];
__device__ float g_logits[kNA];
__device__ float g_logb[kNA];
__device__ float g_f[kNA];
__device__ float g_g[kNT];
__device__ float g_M[67108864];
__device__ float g_pm[kSeg * kNT];
__device__ float g_ps[kSeg * kNT];
__device__ int   g_cnt[32];
__device__ __nv_bfloat16 g_qs[2][kNA * kD];
__device__ __nv_bfloat16 g_ks[2][kNT * kD];

// ---------------- helpers ----------------
__device__ __forceinline__ uint32_t smem_u32(const void* p) {
    uint32_t a;
    asm("{ .reg .u64 t; cvta.to.shared.u64 t, %1; cvt.u32.u64 %0, t; }" : "=r"(a) : "l"(p));
    return a;
}
__device__ __forceinline__ void cp16(uint32_t s, const void* g) {
    asm volatile("cp.async.cg.shared.global [%0], [%1], 16;" :: "r"(s), "l"(g));
}
__device__ __forceinline__ void ldm4(uint32_t& r0, uint32_t& r1, uint32_t& r2,
                                     uint32_t& r3, uint32_t a) {
    asm volatile("ldmatrix.sync.aligned.m8n8.x4.shared.b16 {%0,%1,%2,%3}, [%4];"
                 : "=r"(r0), "=r"(r1), "=r"(r2), "=r"(r3) : "r"(a));
}
__device__ __forceinline__ void mma16816(float* c, const uint32_t* a, const uint32_t* b) {
    asm volatile("mma.sync.aligned.m16n8k16.row.col.f32.bf16.bf16.f32 "
                 "{%0,%1,%2,%3}, {%4,%5,%6,%7}, {%8,%9}, {%0,%1,%2,%3};"
                 : "+f"(c[0]), "+f"(c[1]), "+f"(c[2]), "+f"(c[3])
                 : "r"(a[0]), "r"(a[1]), "r"(a[2]), "r"(a[3]), "r"(b[0]), "r"(b[1]));
}

// ---------------- small SIMT GEMM (q,k,h) ----------------
template<bool RELU>
__global__ void __launch_bounds__(256, 2) gemm128_kernel(
    const float* __restrict__ A, const float* __restrict__ B,
    const float* __restrict__ bias, float* __restrict__ C, int N, int K)
{
    __shared__ float As[16][130];
    __shared__ float Bs[16][130];
    const int tid = threadIdx.x, tx = tid & 15, ty = tid >> 4;
    const int m0 = blockIdx.y * 128, n0 = blockIdx.x * 128;
    const int lr = tid >> 2, lk = (tid & 3) << 2;
    float acc[8][8];
#pragma unroll
    for (int i = 0; i < 8; i++)
#pragma unroll
        for (int j = 0; j < 8; j++) acc[i][j] = 0.f;
    for (int k0 = 0; k0 < K; k0 += 16) {
#pragma unroll
        for (int h = 0; h < 2; h++) {
            int row = lr + h * 64;
            float4 v = *reinterpret_cast<const float4*>(A + (size_t)(m0 + row) * K + k0 + lk);
            As[lk + 0][row] = v.x; As[lk + 1][row] = v.y;
            As[lk + 2][row] = v.z; As[lk + 3][row] = v.w;
        }
        {
            int kk = tid >> 4, nx = (tid & 15) << 2;
#pragma unroll
            for (int h = 0; h < 2; h++) {
                int n = nx + h * 64;
                float4 v = *reinterpret_cast<const float4*>(B + (size_t)(k0 + kk) * N + n0 + n);
                Bs[kk][n + 0] = v.x; Bs[kk][n + 1] = v.y;
                Bs[kk][n + 2] = v.z; Bs[kk][n + 3] = v.w;
            }
        }
        __syncthreads();
#pragma unroll
        for (int kk = 0; kk < 16; kk++) {
            float a[8], b[8];
#pragma unroll
            for (int e = 0; e < 4; e++) {
                a[e] = As[kk][ty * 4 + e];     a[e + 4] = As[kk][ty * 4 + 64 + e];
                b[e] = Bs[kk][tx * 4 + e];     b[e + 4] = Bs[kk][tx * 4 + 64 + e];
            }
#pragma unroll
            for (int i = 0; i < 8; i++)
#pragma unroll
                for (int j = 0; j < 8; j++) acc[i][j] += a[i] * b[j];
        }
        __syncthreads();
    }
#pragma unroll
    for (int i = 0; i < 8; i++) {
        int row = m0 + ty * 4 + (i < 4 ? i : i - 4 + 64);
#pragma unroll
        for (int jh = 0; jh < 2; jh++) {
            int col = n0 + tx * 4 + jh * 64;
            float4 v;
            v.x = acc[i][jh * 4 + 0] + bias[col + 0];
            v.y = acc[i][jh * 4 + 1] + bias[col + 1];
            v.z = acc[i][jh * 4 + 2] + bias[col + 2];
            v.w = acc[i][jh * 4 + 3] + bias[col + 3];
            if (RELU) {
                v.x = fmaxf(v.x, 0.f); v.y = fmaxf(v.y, 0.f);
                v.z = fmaxf(v.z, 0.f); v.w = fmaxf(v.w, 0.f);
            }
            *reinterpret_cast<float4*>(C + (size_t)row * N + col) = v;
        }
    }
}

// ---------------- bf16x2 split (hi + lo) ----------------
__global__ void __launch_bounds__(256) split2_kernel(
    const float* __restrict__ x, __nv_bfloat16* __restrict__ h0,
    __nv_bfloat16* __restrict__ l0)
{
    int i = (blockIdx.x * 256 + threadIdx.x) * 4;
    float4 v = *reinterpret_cast<const float4*>(x + i);
    float vs[4] = {v.x, v.y, v.z, v.w};
    __nv_bfloat16 hh[4], ll[4];
#pragma unroll
    for (int c = 0; c < 4; c++) {
        __nv_bfloat16 h = __float2bfloat16(vs[c]);
        float r = vs[c] - __bfloat162float(h);
        hh[c] = h; ll[c] = __float2bfloat16(r);
    }
    *reinterpret_cast<__nv_bfloat162*>(h0 + i)     = __nv_bfloat162{hh[0], hh[1]};
    *reinterpret_cast<__nv_bfloat162*>(h0 + i + 2) = __nv_bfloat162{hh[2], hh[3]};
    *reinterpret_cast<__nv_bfloat162*>(l0 + i)     = __nv_bfloat162{ll[0], ll[1]};
    *reinterpret_cast<__nv_bfloat162*>(l0 + i + 2) = __nv_bfloat162{ll[2], ll[3]};
}

// ---------------- mma.sync GEMM: M = -20 q k^T (bf16x2, 4 terms) -----------
#define CH_BYTES 20480
#define MG_SMEM  40960

__device__ __forceinline__ void ld_chunk(int c, int m0, int n0, uint32_t sb, int tid)
{
    int term = c >> 3, kc = (c & 7) * 32;
    int at = term >> 1;          // {0,0,1,1}
    int bt = term & 1;           // {0,1,0,1}
    const __nv_bfloat16* A = &g_qs[at][0] + (size_t)m0 * kD + kc;
    const __nv_bfloat16* B = &g_ks[bt][0] + (size_t)n0 * kD + kc;
    uint32_t base = sb + (c & 1) * CH_BYTES;
#pragma unroll
    for (int i = 0; i < 4; i++) {
        int idx = i * 256 + tid;
        int mat = idx >> 9, j = idx & 511;
        int row = j >> 2, seg = j & 3;
        const __nv_bfloat16* src = (mat ? B : A) + (size_t)row * kD + seg * 8;
        cp16(base + mat * 10240 + row * 80 + seg * 16, src);
    }
    asm volatile("cp.async.commit_group;" ::: "memory");
}

__global__ void __launch_bounds__(256) mgemm_kernel()
{
    extern __shared__ char smem[];
    uint32_t sb = smem_u32(smem);
    const int tid = threadIdx.x, wid = tid >> 5, lane = tid & 31;
    const int wm = wid & 1, wn = wid >> 1;
    const int m0 = blockIdx.y * 128, n0 = blockIdx.x * 128;

    float acc[4][4][4];
#pragma unroll
    for (int i = 0; i < 4; i++)
#pragma unroll
        for (int j = 0; j < 4; j++)
#pragma unroll
            for (int e = 0; e < 4; e++) acc[i][j][e] = 0.f;

    const int a_row = lane & 15;
    const int a_kb  = (lane >> 4) * 16;
    const int b_row = (lane & 7) + ((lane >> 4) << 3);
    const int b_kb  = ((lane >> 3) & 1) * 16;

    ld_chunk(0, m0, n0, sb, tid);
#pragma unroll 1
    for (int c = 0; c < 32; c++) {
        if (c + 1 < 32) {
            ld_chunk(c + 1, m0, n0, sb, tid);
            asm volatile("cp.async.wait_group 1;" ::: "memory");
        } else {
            asm volatile("cp.async.wait_group 0;" ::: "memory");
        }
        __syncthreads();
        uint32_t bufA = sb + (c & 1) * CH_BYTES;
        uint32_t bufB = bufA + 10240;
#pragma unroll
        for (int ks = 0; ks < 2; ks++) {
            uint32_t afr[4][4], bfr[2][4];
#pragma unroll
            for (int mt = 0; mt < 4; mt++)
                ldm4(afr[mt][0], afr[mt][1], afr[mt][2], afr[mt][3],
                     bufA + (wm * 64 + mt * 16 + a_row) * 80 + ks * 32 + a_kb);
#pragma unroll
            for (int p = 0; p < 2; p++)
                ldm4(bfr[p][0], bfr[p][1], bfr[p][2], bfr[p][3],
                     bufB + (wn * 32 + p * 16 + b_row) * 80 + ks * 32 + b_kb);
#pragma unroll
            for (int mt = 0; mt < 4; mt++)
#pragma unroll
                for (int nt = 0; nt < 4; nt++)
                    mma16816(acc[mt][nt], afr[mt], &bfr[nt >> 1][(nt & 1) * 2]);
        }
        __syncthreads();
    }

    float* stg = reinterpret_cast<float*>(smem);
#pragma unroll 1
    for (int h = 0; h < 2; h++) {
        if (wm == h) {
#pragma unroll
            for (int mt = 0; mt < 4; mt++)
#pragma unroll
                for (int nt = 0; nt < 4; nt++) {
                    int r0 = mt * 16 + (lane >> 2);
                    int cc = wn * 32 + nt * 8 + (lane & 3) * 2;
                    stg[r0 * 132 + cc]           = acc[mt][nt][0];
                    stg[r0 * 132 + cc + 1]       = acc[mt][nt][1];
                    stg[(r0 + 8) * 132 + cc]     = acc[mt][nt][2];
                    stg[(r0 + 8) * 132 + cc + 1] = acc[mt][nt][3];
                }
        }
        __syncthreads();
#pragma unroll
        for (int it = 0; it < 8; it++) {
            int idx = it * 256 + tid;
            int r = idx >> 5, c4 = idx & 31;
            float4 v = *reinterpret_cast<const float4*>(stg + r * 132 + c4 * 4);
            v.x *= -20.f; v.y *= -20.f; v.z *= -20.f; v.w *= -20.f;
            *reinterpret_cast<float4*>(
                g_M + (size_t)(m0 + h * 64 + r) * kNT + n0 + c4 * 4) = v;
        }
        __syncthreads();
    }
}

// ---------------- logits / softmax / g init ----------------
__global__ void logits_kernel(const float* __restrict__ W2, const float* __restrict__ b2)
{
    int warp = threadIdx.x >> 5, lane = threadIdx.x & 31;
    int i = blockIdx.x * 8 + warp;
    const float* hr = g_h + (size_t)i * kH;
    float acc = 0.f;
#pragma unroll
    for (int d = lane; d < kH; d += 32) acc += hr[d] * W2[d];
#pragma unroll
    for (int off = 16; off; off >>= 1) acc += __shfl_down_sync(0xffffffffu, acc, off);
    if (lane == 0) g_logits[i] = acc + b2[0];
}

__global__ void softmax_log_kernel()
{
    __shared__ float red[1024];
    int t = threadIdx.x;
    float m = NEGINF;
    for (int i = t; i < kNA; i += 1024) m = fmaxf(m, g_logits[i]);
    red[t] = m; __syncthreads();
    for (int off = 512; off; off >>= 1) {
        if (t < off) red[t] = fmaxf(red[t], red[t + off]);
        __syncthreads();
    }
    float gm = red[0]; __syncthreads();
    float sum = 0.f;
    for (int i = t; i < kNA; i += 1024) sum += __expf(g_logits[i] - gm);
    red[t] = sum; __syncthreads();
    for (int off = 512; off; off >>= 1) {
        if (t < off) red[t] += red[t + off];
        __syncthreads();
    }
    float lse = gm + logf(red[0]);
    for (int i = t; i < kNA; i += 1024) g_logb[i] = g_logits[i] - lse;
}

__global__ void ginit_kernel()
{
    int warp = threadIdx.x >> 5, lane = threadIdx.x & 31;
    int j = blockIdx.x * 8 + warp;
    const float* kr = g_k + (size_t)j * kD;
    float acc = 0.f;
#pragma unroll
    for (int d = lane; d < kD; d += 32) { float v = kr[d]; acc += v * v; }
#pragma unroll
    for (int off = 16; off; off >>= 1) acc += __shfl_down_sync(0xffffffffu, acc, off);
    if (lane == 0) g_g[j] = INV_EPS * acc;
}

// ---------------- row LSE: 4 rows/block, shfl reduction ----------------
__global__ void __launch_bounds__(256) row_lse_kernel()
{
    const int i0 = blockIdx.x * 4;
    const int t = threadIdx.x;
    const int wid = t >> 5, lane = t & 31;
    const float4* g4 = reinterpret_cast<const float4*>(g_g);
    float m[4], s[4];
#pragma unroll
    for (int r = 0; r < 4; r++) { m[r] = NEGINF; s[r] = 0.f; }
#pragma unroll
    for (int c = 0; c < 8; c++) {
        const int p = c * 256 + t;
        float4 gv = g4[p];
#pragma unroll
        for (int r = 0; r < 4; r++) {
            float4 mv = reinterpret_cast<const float4*>(
                g_M + (size_t)(i0 + r) * kNT)[p];
            float x0 = mv.x + gv.x, x1 = mv.y + gv.y;
            float x2 = mv.z + gv.z, x3 = mv.w + gv.w;
            float lm = fmaxf(fmaxf(x0, x1), fmaxf(x2, x3));
            float mn = fmaxf(m[r], lm);
            float acc = __expf(x0 - mn) + __expf(x1 - mn)
                      + __expf(x2 - mn) + __expf(x3 - mn);
            s[r] = s[r] * __expf(m[r] - mn) + acc;
            m[r] = mn;
        }
    }
    // warp-level reduction (register-only) for all 4 rows
#pragma unroll
    for (int r = 0; r < 4; r++) {
#pragma unroll
        for (int off = 16; off; off >>= 1) {
            float m2 = __shfl_down_sync(0xffffffffu, m[r], off);
            float s2 = __shfl_down_sync(0xffffffffu, s[r], off);
            float mn = fmaxf(m[r], m2);
            s[r] = s[r] * __expf(m[r] - mn) + s2 * __expf(m2 - mn);
            m[r] = mn;
        }
    }
    // 8 warps -> smem, single sync, warp 0 finishes
    __shared__ float wm[4][8], ws[4][8];
    if (lane == 0) {
#pragma unroll
        for (int r = 0; r < 4; r++) { wm[r][wid] = m[r]; ws[r][wid] = s[r]; }
    }
    __syncthreads();
    if (t < 4) {
        int r = t;
        float mm = wm[r][0], ss = ws[r][0];
#pragma unroll
        for (int w = 1; w < 8; w++) {
            float m2 = wm[r][w];
            float mn = fmaxf(mm, m2);
            ss = ss * __expf(mm - mn) + ws[r][w] * __expf(m2 - mn);
            mm = mn;
        }
        g_f[i0 + r] = g_logb[i0 + r] - (mm + logf(ss));
    }
}

// ---------------- column LSE (R12 body) + fused last-block combine ---------
__global__ void __launch_bounds__(256) col_lse_kernel(float log_a)
{
    const int j = blockIdx.x * 256 + threadIdx.x;
    const int seg = blockIdx.y;
    const int r0 = seg * kSegRows;
    __shared__ float fs[kSegRows];
    fs[threadIdx.x] = g_f[r0 + threadIdx.x];
    __syncthreads();
    const float* p = g_M + (size_t)r0 * kNT + j;
    float m = NEGINF, s = 0.f;
    for (int rb = 0; rb < kSegRows; rb += 8) {
        float x[8];
#pragma unroll
        for (int r = 0; r < 8; r++)
            x[r] = p[(size_t)(rb + r) * kNT] + fs[rb + r];
        float lm = x[0];
#pragma unroll
        for (int r = 1; r < 8; r++) lm = fmaxf(lm, x[r]);
        float mn = fmaxf(m, lm);
        float acc = 0.f;
#pragma unroll
        for (int r = 0; r < 8; r++) acc += __expf(x[r] - mn);
        s = s * __expf(m - mn) + acc;
        m = mn;
    }
    g_pm[seg * kNT + j] = m;
    g_ps[seg * kNT + j] = s;

    // last block of this column tile combines all 32 segment partials into g
    __threadfence();
    __syncthreads();
    __shared__ int isLast;
    if (threadIdx.x == 0) {
        int d = atomicAdd(&g_cnt[blockIdx.x], 1);
        isLast = (d == kSeg - 1);
    }
    __syncthreads();
    if (isLast) {
        __threadfence();
        float mm = NEGINF;
#pragma unroll
        for (int sg = 0; sg < kSeg; sg++) mm = fmaxf(mm, g_pm[sg * kNT + j]);
        float acc = 0.f;
#pragma unroll
        for (int sg = 0; sg < kSeg; sg++)
            acc += g_ps[sg * kNT + j] * __expf(g_pm[sg * kNT + j] - mm);
        g_g[j] = log_a - (mm + logf(acc));
        __syncthreads();
        if (threadIdx.x == 0) g_cnt[blockIdx.x] = 0;   // graph-replay-safe reset
    }
}

// ---------------- final T ----------------
__global__ void __launch_bounds__(256) final_T_kernel(float* __restrict__ out,
                                                      float inv_total)
{
    int i = blockIdx.y;
    int p = blockIdx.x * 256 + threadIdx.x;
    float fi = g_f[i];
    float4 mv = reinterpret_cast<const float4*>(g_M + (size_t)i * kNT)[p];
    float4 gv = reinterpret_cast<const float4*>(g_g)[p];
    float4 o;
    o.x = __expf((fi + gv.x) + mv.x) * inv_total;
    o.y = __expf((fi + gv.y) + mv.y) * inv_total;
    o.z = __expf((fi + gv.z) + mv.z) * inv_total;
    o.w = __expf((fi + gv.w) + mv.w) * inv_total;
    reinterpret_cast<float4*>(out + (size_t)i * kNT)[p] = o;
}

// ---------------- host ----------------
extern "C" void kernel_launch(void* const* d_in, const int* in_sizes, int n_in,
                              void* d_out, int out_size)
{
    const float* Aemb = (const float*)d_in[0];
    const float* Temb = (const float*)d_in[1];
    const float* Wq   = (const float*)d_in[2];
    const float* bq   = (const float*)d_in[3];
    const float* Wk   = (const float*)d_in[4];
    const float* bk   = (const float*)d_in[5];
    const float* W1   = (const float*)d_in[6];
    const float* b1   = (const float*)d_in[7];
    const float* W2   = (const float*)d_in[8];
    const float* b2   = (const float*)d_in[9];
    float* out = (float*)d_out;

    float *pq, *pk, *ph;
    __nv_bfloat16 *pqs, *pks;
    cudaGetSymbolAddress((void**)&pq, g_q);
    cudaGetSymbolAddress((void**)&pk, g_k);
    cudaGetSymbolAddress((void**)&ph, g_h);
    cudaGetSymbolAddress((void**)&pqs, g_qs);
    cudaGetSymbolAddress((void**)&pks, g_ks);

    gemm128_kernel<false><<<dim3(2, 64), 256>>>(Aemb, Wq, bq, pq, 256, 256);
    gemm128_kernel<false><<<dim3(2, 64), 256>>>(Temb, Wk, bk, pk, 256, 256);
    gemm128_kernel<true ><<<dim3(1, 64), 256>>>(Aemb, W1, b1, ph, 128, 256);
    logits_kernel<<<1024, 256>>>(W2, b2);
    softmax_log_kernel<<<1, 1024>>>();
    ginit_kernel<<<1024, 256>>>();

    split2_kernel<<<2048, 256>>>(pq, pqs, pqs + kNA * kD);
    split2_kernel<<<2048, 256>>>(pk, pks, pks + kNT * kD);

    mgemm_kernel<<<dim3(64, 64), 256, MG_SMEM>>>();

    const float log_a = logf(1.0f / 8192.0f + 1e-20f);
    for (int it = 0; it < 50; it++) {
        row_lse_kernel<<<2048, 256>>>();
        col_lse_kernel<<<dim3(32, 32), 256>>>(log_a);
    }
    final_T_kernel<<<dim3(8, 8192), 256>>>(out, 1.0f / (1.0f + 1e-8f));
}

// round 15
// speedup vs baseline: 1.5593x; 1.1751x over previous
#include <cuda_runtime.h>
#include <cuda_bf16.h>
#include <math.h>
#include <stdint.h>

#define kNA 8192
#define kNT 8192
#define kD  256
#define kH  128
#define kSeg 32
#define kSegRows 256
#define INV_EPS 10.0f
#define NEGINF -3.402823466e38f

__device__ float g_q[kNA * kD];
__device__ float g_k[kNT * kD];
__device__ float g_h[kNA * kH];
__device__ float g_logits[kNA];
__device__ float g_logb[kNA];
__device__ float g_f[kNA];
__device__ float g_g[kNT];
__device__ float g_M[67108864];
__device__ float g_pm[kSeg * kNT];
__device__ float g_ps[kSeg * kNT];
__device__ __nv_bfloat16 g_qs[2][kNA * kD];
__device__ __nv_bfloat16 g_ks[2][kNT * kD];

// ---------------- helpers ----------------
__device__ __forceinline__ uint32_t smem_u32(const void* p) {
    uint32_t a;
    asm("{ .reg .u64 t; cvta.to.shared.u64 t, %1; cvt.u32.u64 %0, t; }" : "=r"(a) : "l"(p));
    return a;
}
__device__ __forceinline__ void cp16(uint32_t s, const void* g) {
    asm volatile("cp.async.cg.shared.global [%0], [%1], 16;" :: "r"(s), "l"(g));
}
__device__ __forceinline__ void ldm4(uint32_t& r0, uint32_t& r1, uint32_t& r2,
                                     uint32_t& r3, uint32_t a) {
    asm volatile("ldmatrix.sync.aligned.m8n8.x4.shared.b16 {%0,%1,%2,%3}, [%4];"
                 : "=r"(r0), "=r"(r1), "=r"(r2), "=r"(r3) : "r"(a));
}
__device__ __forceinline__ void mma16816(float* c, const uint32_t* a, const uint32_t* b) {
    asm volatile("mma.sync.aligned.m16n8k16.row.col.f32.bf16.bf16.f32 "
                 "{%0,%1,%2,%3}, {%4,%5,%6,%7}, {%8,%9}, {%0,%1,%2,%3};"
                 : "+f"(c[0]), "+f"(c[1]), "+f"(c[2]), "+f"(c[3])
                 : "r"(a[0]), "r"(a[1]), "r"(a[2]), "r"(a[3]), "r"(b[0]), "r"(b[1]));
}

// ---------------- small SIMT GEMM (q,k,h) ----------------
template<bool RELU>
__global__ void __launch_bounds__(256, 2) gemm128_kernel(
    const float* __restrict__ A, const float* __restrict__ B,
    const float* __restrict__ bias, float* __restrict__ C, int N, int K)
{
    __shared__ float As[16][130];
    __shared__ float Bs[16][130];
    const int tid = threadIdx.x, tx = tid & 15, ty = tid >> 4;
    const int m0 = blockIdx.y * 128, n0 = blockIdx.x * 128;
    const int lr = tid >> 2, lk = (tid & 3) << 2;
    float acc[8][8];
#pragma unroll
    for (int i = 0; i < 8; i++)
#pragma unroll
        for (int j = 0; j < 8; j++) acc[i][j] = 0.f;
    for (int k0 = 0; k0 < K; k0 += 16) {
#pragma unroll
        for (int h = 0; h < 2; h++) {
            int row = lr + h * 64;
            float4 v = *reinterpret_cast<const float4*>(A + (size_t)(m0 + row) * K + k0 + lk);
            As[lk + 0][row] = v.x; As[lk + 1][row] = v.y;
            As[lk + 2][row] = v.z; As[lk + 3][row] = v.w;
        }
        {
            int kk = tid >> 4, nx = (tid & 15) << 2;
#pragma unroll
            for (int h = 0; h < 2; h++) {
                int n = nx + h * 64;
                float4 v = *reinterpret_cast<const float4*>(B + (size_t)(k0 + kk) * N + n0 + n);
                Bs[kk][n + 0] = v.x; Bs[kk][n + 1] = v.y;
                Bs[kk][n + 2] = v.z; Bs[kk][n + 3] = v.w;
            }
        }
        __syncthreads();
#pragma unroll
        for (int kk = 0; kk < 16; kk++) {
            float a[8], b[8];
#pragma unroll
            for (int e = 0; e < 4; e++) {
                a[e] = As[kk][ty * 4 + e];     a[e + 4] = As[kk][ty * 4 + 64 + e];
                b[e] = Bs[kk][tx * 4 + e];     b[e + 4] = Bs[kk][tx * 4 + 64 + e];
            }
#pragma unroll
            for (int i = 0; i < 8; i++)
#pragma unroll
                for (int j = 0; j < 8; j++) acc[i][j] += a[i] * b[j];
        }
        __syncthreads();
    }
#pragma unroll
    for (int i = 0; i < 8; i++) {
        int row = m0 + ty * 4 + (i < 4 ? i : i - 4 + 64);
#pragma unroll
        for (int jh = 0; jh < 2; jh++) {
            int col = n0 + tx * 4 + jh * 64;
            float4 v;
            v.x = acc[i][jh * 4 + 0] + bias[col + 0];
            v.y = acc[i][jh * 4 + 1] + bias[col + 1];
            v.z = acc[i][jh * 4 + 2] + bias[col + 2];
            v.w = acc[i][jh * 4 + 3] + bias[col + 3];
            if (RELU) {
                v.x = fmaxf(v.x, 0.f); v.y = fmaxf(v.y, 0.f);
                v.z = fmaxf(v.z, 0.f); v.w = fmaxf(v.w, 0.f);
            }
            *reinterpret_cast<float4*>(C + (size_t)row * N + col) = v;
        }
    }
}

// ---------------- bf16x2 split (hi + lo) ----------------
__global__ void __launch_bounds__(256) split2_kernel(
    const float* __restrict__ x, __nv_bfloat16* __restrict__ h0,
    __nv_bfloat16* __restrict__ l0)
{
    int i = (blockIdx.x * 256 + threadIdx.x) * 4;
    float4 v = *reinterpret_cast<const float4*>(x + i);
    float vs[4] = {v.x, v.y, v.z, v.w};
    __nv_bfloat16 hh[4], ll[4];
#pragma unroll
    for (int c = 0; c < 4; c++) {
        __nv_bfloat16 h = __float2bfloat16(vs[c]);
        float r = vs[c] - __bfloat162float(h);
        hh[c] = h; ll[c] = __float2bfloat16(r);
    }
    *reinterpret_cast<__nv_bfloat162*>(h0 + i)     = __nv_bfloat162{hh[0], hh[1]};
    *reinterpret_cast<__nv_bfloat162*>(h0 + i + 2) = __nv_bfloat162{hh[2], hh[3]};
    *reinterpret_cast<__nv_bfloat162*>(l0 + i)     = __nv_bfloat162{ll[0], ll[1]};
    *reinterpret_cast<__nv_bfloat162*>(l0 + i + 2) = __nv_bfloat162{ll[2], ll[3]};
}

// ---------------- mma.sync GEMM: M = -20 q k^T (bf16x2, 4 terms) -----------
#define CH_BYTES 20480
#define MG_SMEM  40960

__device__ __forceinline__ void ld_chunk(int c, int m0, int n0, uint32_t sb, int tid)
{
    int term = c >> 3, kc = (c & 7) * 32;
    int at = term >> 1;          // {0,0,1,1}
    int bt = term & 1;           // {0,1,0,1}
    const __nv_bfloat16* A = &g_qs[at][0] + (size_t)m0 * kD + kc;
    const __nv_bfloat16* B = &g_ks[bt][0] + (size_t)n0 * kD + kc;
    uint32_t base = sb + (c & 1) * CH_BYTES;
#pragma unroll
    for (int i = 0; i < 4; i++) {
        int idx = i * 256 + tid;
        int mat = idx >> 9, j = idx & 511;
        int row = j >> 2, seg = j & 3;
        const __nv_bfloat16* src = (mat ? B : A) + (size_t)row * kD + seg * 8;
        cp16(base + mat * 10240 + row * 80 + seg * 16, src);
    }
    asm volatile("cp.async.commit_group;" ::: "memory");
}

__global__ void __launch_bounds__(256) mgemm_kernel()
{
    extern __shared__ char smem[];
    uint32_t sb = smem_u32(smem);
    const int tid = threadIdx.x, wid = tid >> 5, lane = tid & 31;
    const int wm = wid & 1, wn = wid >> 1;
    const int m0 = blockIdx.y * 128, n0 = blockIdx.x * 128;

    float acc[4][4][4];
#pragma unroll
    for (int i = 0; i < 4; i++)
#pragma unroll
        for (int j = 0; j < 4; j++)
#pragma unroll
            for (int e = 0; e < 4; e++) acc[i][j][e] = 0.f;

    const int a_row = lane & 15;
    const int a_kb  = (lane >> 4) * 16;
    const int b_row = (lane & 7) + ((lane >> 4) << 3);
    const int b_kb  = ((lane >> 3) & 1) * 16;

    ld_chunk(0, m0, n0, sb, tid);
#pragma unroll 1
    for (int c = 0; c < 32; c++) {
        if (c + 1 < 32) {
            ld_chunk(c + 1, m0, n0, sb, tid);
            asm volatile("cp.async.wait_group 1;" ::: "memory");
        } else {
            asm volatile("cp.async.wait_group 0;" ::: "memory");
        }
        __syncthreads();
        uint32_t bufA = sb + (c & 1) * CH_BYTES;
        uint32_t bufB = bufA + 10240;
#pragma unroll
        for (int ks = 0; ks < 2; ks++) {
            uint32_t afr[4][4], bfr[2][4];
#pragma unroll
            for (int mt = 0; mt < 4; mt++)
                ldm4(afr[mt][0], afr[mt][1], afr[mt][2], afr[mt][3],
                     bufA + (wm * 64 + mt * 16 + a_row) * 80 + ks * 32 + a_kb);
#pragma unroll
            for (int p = 0; p < 2; p++)
                ldm4(bfr[p][0], bfr[p][1], bfr[p][2], bfr[p][3],
                     bufB + (wn * 32 + p * 16 + b_row) * 80 + ks * 32 + b_kb);
#pragma unroll
            for (int mt = 0; mt < 4; mt++)
#pragma unroll
                for (int nt = 0; nt < 4; nt++)
                    mma16816(acc[mt][nt], afr[mt], &bfr[nt >> 1][(nt & 1) * 2]);
        }
        __syncthreads();
    }

    float* stg = reinterpret_cast<float*>(smem);
#pragma unroll 1
    for (int h = 0; h < 2; h++) {
        if (wm == h) {
#pragma unroll
            for (int mt = 0; mt < 4; mt++)
#pragma unroll
                for (int nt = 0; nt < 4; nt++) {
                    int r0 = mt * 16 + (lane >> 2);
                    int cc = wn * 32 + nt * 8 + (lane & 3) * 2;
                    stg[r0 * 132 + cc]           = acc[mt][nt][0];
                    stg[r0 * 132 + cc + 1]       = acc[mt][nt][1];
                    stg[(r0 + 8) * 132 + cc]     = acc[mt][nt][2];
                    stg[(r0 + 8) * 132 + cc + 1] = acc[mt][nt][3];
                }
        }
        __syncthreads();
#pragma unroll
        for (int it = 0; it < 8; it++) {
            int idx = it * 256 + tid;
            int r = idx >> 5, c4 = idx & 31;
            float4 v = *reinterpret_cast<const float4*>(stg + r * 132 + c4 * 4);
            v.x *= -20.f; v.y *= -20.f; v.z *= -20.f; v.w *= -20.f;
            *reinterpret_cast<float4*>(
                g_M + (size_t)(m0 + h * 64 + r) * kNT + n0 + c4 * 4) = v;
        }
        __syncthreads();
    }
}

// ---------------- logits / softmax / g init ----------------
__global__ void logits_kernel(const float* __restrict__ W2, const float* __restrict__ b2)
{
    int warp = threadIdx.x >> 5, lane = threadIdx.x & 31;
    int i = blockIdx.x * 8 + warp;
    const float* hr = g_h + (size_t)i * kH;
    float acc = 0.f;
#pragma unroll
    for (int d = lane; d < kH; d += 32) acc += hr[d] * W2[d];
#pragma unroll
    for (int off = 16; off; off >>= 1) acc += __shfl_down_sync(0xffffffffu, acc, off);
    if (lane == 0) g_logits[i] = acc + b2[0];
}

__global__ void softmax_log_kernel()
{
    __shared__ float red[1024];
    int t = threadIdx.x;
    float m = NEGINF;
    for (int i = t; i < kNA; i += 1024) m = fmaxf(m, g_logits[i]);
    red[t] = m; __syncthreads();
    for (int off = 512; off; off >>= 1) {
        if (t < off) red[t] = fmaxf(red[t], red[t + off]);
        __syncthreads();
    }
    float gm = red[0]; __syncthreads();
    float sum = 0.f;
    for (int i = t; i < kNA; i += 1024) sum += __expf(g_logits[i] - gm);
    red[t] = sum; __syncthreads();
    for (int off = 512; off; off >>= 1) {
        if (t < off) red[t] += red[t + off];
        __syncthreads();
    }
    float lse = gm + logf(red[0]);
    for (int i = t; i < kNA; i += 1024) g_logb[i] = g_logits[i] - lse;
}

__global__ void ginit_kernel()
{
    int warp = threadIdx.x >> 5, lane = threadIdx.x & 31;
    int j = blockIdx.x * 8 + warp;
    const float* kr = g_k + (size_t)j * kD;
    float acc = 0.f;
#pragma unroll
    for (int d = lane; d < kD; d += 32) { float v = kr[d]; acc += v * v; }
#pragma unroll
    for (int off = 16; off; off >>= 1) acc += __shfl_down_sync(0xffffffffu, acc, off);
    if (lane == 0) g_g[j] = INV_EPS * acc;
}

// ---------------- row LSE: 4 rows/block, shfl reduction (single change) -----
__global__ void __launch_bounds__(256) row_lse_kernel()
{
    const int i0 = blockIdx.x * 4;
    const int t = threadIdx.x;
    const int wid = t >> 5, lane = t & 31;
    const float4* g4 = reinterpret_cast<const float4*>(g_g);
    float m[4], s[4];
#pragma unroll
    for (int r = 0; r < 4; r++) { m[r] = NEGINF; s[r] = 0.f; }
#pragma unroll
    for (int c = 0; c < 8; c++) {
        const int p = c * 256 + t;
        float4 gv = g4[p];
#pragma unroll
        for (int r = 0; r < 4; r++) {
            float4 mv = reinterpret_cast<const float4*>(
                g_M + (size_t)(i0 + r) * kNT)[p];
            float x0 = mv.x + gv.x, x1 = mv.y + gv.y;
            float x2 = mv.z + gv.z, x3 = mv.w + gv.w;
            float lm = fmaxf(fmaxf(x0, x1), fmaxf(x2, x3));
            float mn = fmaxf(m[r], lm);
            float acc = __expf(x0 - mn) + __expf(x1 - mn)
                      + __expf(x2 - mn) + __expf(x3 - mn);
            s[r] = s[r] * __expf(m[r] - mn) + acc;
            m[r] = mn;
        }
    }
    // register-only warp reduction for all 4 rows
#pragma unroll
    for (int r = 0; r < 4; r++) {
#pragma unroll
        for (int off = 16; off; off >>= 1) {
            float m2 = __shfl_down_sync(0xffffffffu, m[r], off);
            float s2 = __shfl_down_sync(0xffffffffu, s[r], off);
            float mn = fmaxf(m[r], m2);
            s[r] = s[r] * __expf(m[r] - mn) + s2 * __expf(m2 - mn);
            m[r] = mn;
        }
    }
    // 8 warp leaders -> smem, one sync, 4 threads finish
    __shared__ float wm[4][8], ws[4][8];
    if (lane == 0) {
#pragma unroll
        for (int r = 0; r < 4; r++) { wm[r][wid] = m[r]; ws[r][wid] = s[r]; }
    }
    __syncthreads();
    if (t < 4) {
        int r = t;
        float mm = wm[r][0], ss = ws[r][0];
#pragma unroll
        for (int w = 1; w < 8; w++) {
            float m2 = wm[r][w];
            float mn = fmaxf(mm, m2);
            ss = ss * __expf(mm - mn) + ws[r][w] * __expf(m2 - mn);
            mm = mn;
        }
        g_f[i0 + r] = g_logb[i0 + r] - (mm + logf(ss));
    }
}

// ---------------- column LSE (R12-exact): 1 col/thread, scalar --------------
__global__ void __launch_bounds__(256) col_lse_kernel()
{
    const int j = blockIdx.x * 256 + threadIdx.x;
    const int seg = blockIdx.y;
    const int r0 = seg * kSegRows;
    __shared__ float fs[kSegRows];
    fs[threadIdx.x] = g_f[r0 + threadIdx.x];
    __syncthreads();
    const float* p = g_M + (size_t)r0 * kNT + j;
    float m = NEGINF, s = 0.f;
    for (int rb = 0; rb < kSegRows; rb += 8) {
        float x[8];
#pragma unroll
        for (int r = 0; r < 8; r++)
            x[r] = p[(size_t)(rb + r) * kNT] + fs[rb + r];
        float lm = x[0];
#pragma unroll
        for (int r = 1; r < 8; r++) lm = fmaxf(lm, x[r]);
        float mn = fmaxf(m, lm);
        float acc = 0.f;
#pragma unroll
        for (int r = 0; r < 8; r++) acc += __expf(x[r] - mn);
        s = s * __expf(m - mn) + acc;
        m = mn;
    }
    g_pm[seg * kNT + j] = m;
    g_ps[seg * kNT + j] = s;
}

__global__ void col_combine_kernel(float log_a)
{
    int j = blockIdx.x * 256 + threadIdx.x;
    float m = NEGINF;
#pragma unroll
    for (int sg = 0; sg < kSeg; sg++) m = fmaxf(m, g_pm[sg * kNT + j]);
    float acc = 0.f;
#pragma unroll
    for (int sg = 0; sg < kSeg; sg++)
        acc += g_ps[sg * kNT + j] * __expf(g_pm[sg * kNT + j] - m);
    g_g[j] = log_a - (m + logf(acc));
}

// ---------------- final T ----------------
__global__ void __launch_bounds__(256) final_T_kernel(float* __restrict__ out,
                                                      float inv_total)
{
    int i = blockIdx.y;
    int p = blockIdx.x * 256 + threadIdx.x;   // float4 index
    float fi = g_f[i];
    float4 mv = reinterpret_cast<const float4*>(g_M + (size_t)i * kNT)[p];
    float4 gv = reinterpret_cast<const float4*>(g_g)[p];
    float4 o;
    o.x = __expf((fi + gv.x) + mv.x) * inv_total;
    o.y = __expf((fi + gv.y) + mv.y) * inv_total;
    o.z = __expf((fi + gv.z) + mv.z) * inv_total;
    o.w = __expf((fi + gv.w) + mv.w) * inv_total;
    reinterpret_cast<float4*>(out + (size_t)i * kNT)[p] = o;
}

// ---------------- host ----------------
extern "C" void kernel_launch(void* const* d_in, const int* in_sizes, int n_in,
                              void* d_out, int out_size)
{
    const float* Aemb = (const float*)d_in[0];
    const float* Temb = (const float*)d_in[1];
    const float* Wq   = (const float*)d_in[2];
    const float* bq   = (const float*)d_in[3];
    const float* Wk   = (const float*)d_in[4];
    const float* bk   = (const float*)d_in[5];
    const float* W1   = (const float*)d_in[6];
    const float* b1   = (const float*)d_in[7];
    const float* W2   = (const float*)d_in[8];
    const float* b2   = (const float*)d_in[9];
    float* out = (float*)d_out;

    float *pq, *pk, *ph;
    __nv_bfloat16 *pqs, *pks;
    cudaGetSymbolAddress((void**)&pq, g_q);
    cudaGetSymbolAddress((void**)&pk, g_k);
    cudaGetSymbolAddress((void**)&ph, g_h);
    cudaGetSymbolAddress((void**)&pqs, g_qs);
    cudaGetSymbolAddress((void**)&pks, g_ks);

    gemm128_kernel<false><<<dim3(2, 64), 256>>>(Aemb, Wq, bq, pq, 256, 256);
    gemm128_kernel<false><<<dim3(2, 64), 256>>>(Temb, Wk, bk, pk, 256, 256);
    gemm128_kernel<true ><<<dim3(1, 64), 256>>>(Aemb, W1, b1, ph, 128, 256);
    logits_kernel<<<1024, 256>>>(W2, b2);
    softmax_log_kernel<<<1, 1024>>>();
    ginit_kernel<<<1024, 256>>>();

    split2_kernel<<<2048, 256>>>(pq, pqs, pqs + kNA * kD);
    split2_kernel<<<2048, 256>>>(pk, pks, pks + kNT * kD);

    mgemm_kernel<<<dim3(64, 64), 256, MG_SMEM>>>();

    const float log_a = logf(1.0f / 8192.0f + 1e-20f);
    for (int it = 0; it < 50; it++) {
        row_lse_kernel<<<2048, 256>>>();
        col_lse_kernel<<<dim3(32, 32), 256>>>();
        col_combine_kernel<<<32, 256>>>(log_a);
    }
    final_T_kernel<<<dim3(8, 8192), 256>>>(out, 1.0f / (1.0f + 1e-8f));
}